// round 3
// baseline (speedup 1.0000x reference)
#include <cuda_runtime.h>

#define NN  100000
#define EE  800000
#define DD  96
#define NRD 102   // D + XD

typedef unsigned long long u64;

__device__ __forceinline__ u64 ffma2(u64 a, u64 b, u64 c) {
    u64 d; asm("fma.rn.f32x2 %0,%1,%2,%3;" : "=l"(d) : "l"(a), "l"(b), "l"(c)); return d;
}
__device__ __forceinline__ float2 up2(u64 v) {
    float2 f; asm("mov.b64 {%0,%1},%2;" : "=f"(f.x), "=f"(f.y) : "l"(v)); return f;
}

// ---- scratch (device globals; no allocation allowed) ----
__device__ __align__(16) float4 g_num4[NN * 24];   // [N,96] accumulator
__device__ float  g_den[NN];
__device__ __align__(16) float g_P[NN * DD];       // node_rep @ W1^T
__device__ __align__(16) float g_Q[NN * DD];       // node_rep @ W2^T

// ---------------------------------------------------------------------------
// K0: zero accumulators, write x into node_rep columns 96..101
// ---------------------------------------------------------------------------
__global__ void init_k(const float* __restrict__ x, float* __restrict__ node_out) {
    int i = blockIdx.x * 256 + threadIdx.x;
    if (i < NN * 24) g_num4[i] = make_float4(0.f, 0.f, 0.f, 0.f);
    if (i < NN)      g_den[i] = 0.f;
    if (i < NN * 6)  node_out[(i / 6) * NRD + 96 + (i % 6)] = x[i];
}

// ---------------------------------------------------------------------------
// K1: masked scatter-sum via vector reduction atomics (one thread per quad)
// ---------------------------------------------------------------------------
__global__ void scatter_k(const int* __restrict__ ei,
                          const float* __restrict__ attr,
                          const float* __restrict__ mask) {
    int i = blockIdx.x * 256 + threadIdx.x;
    if (i >= EE * 24) return;
    int e = i / 24;
    int q = i - e * 24;
    int c = ei[EE + e];
    float m = mask[e];
    float4 v = *(const float4*)(attr + (size_t)e * 96 + q * 4);
    float* dst = ((float*)g_num4) + (size_t)c * 96 + q * 4;
    asm volatile("red.global.add.v4.f32 [%0], {%1,%2,%3,%4};"
                 :: "l"(dst), "f"(v.x * m), "f"(v.y * m), "f"(v.z * m), "f"(v.w * m)
                 : "memory");
    if (q == 0) atomicAdd(&g_den[c], m);
}

// ---------------------------------------------------------------------------
// K2: node_rep[:, :96] = num / (den + 1)
// ---------------------------------------------------------------------------
__global__ void finalize_k(float* __restrict__ node_out) {
    int i = blockIdx.x * 256 + threadIdx.x;
    if (i >= NN * 24) return;
    int n = i / 24;
    int q = i - n * 24;
    float inv = 1.f / (g_den[n] + 1.f);
    float4 v = g_num4[i];
    float* dst = node_out + (size_t)n * NRD + q * 4;
    dst[0] = v.x * inv; dst[1] = v.y * inv; dst[2] = v.z * inv; dst[3] = v.w * inv;
}

// ---------------------------------------------------------------------------
// K3: tail-row blend, parallel: gather-all -> sync -> write-all (one block)
// ---------------------------------------------------------------------------
__global__ void blend_k(const int* __restrict__ change,
                        const int* __restrict__ is_support,
                        const int* __restrict__ tails,
                        const float* __restrict__ support_tail,
                        float* __restrict__ node_out) {
    if (change[0] == 0) return;
    const int TOT = 128 * NRD;                 // 13056
    int tid = threadIdx.x;                     // 0..1023
    float vals[13];
    int   addr[13];
    short dim[13];
    int cnt = 0;
    for (int i = tid; i < TOT; i += 1024) {
        int t = i / NRD, d = i - t * NRD;
        int node = tails[t];
        addr[cnt] = node * NRD + d;
        dim[cnt]  = (short)d;
        vals[cnt] = node_out[addr[cnt]];
        cnt++;
    }
    if (is_support[0]) {
        __shared__ float ssum[NRD];
        for (int d = tid; d < NRD; d += 1024) ssum[d] = 0.f;
        __syncthreads();
        for (int j = 0; j < cnt; j++) atomicAdd(&ssum[dim[j]], vals[j]);
        __syncthreads();
        for (int j = 0; j < cnt; j++)
            node_out[addr[j]] = ssum[dim[j]] * (1.f / 128.f);
    } else {
        __syncthreads();                       // all gathers before any write
        for (int j = 0; j < cnt; j++)
            node_out[addr[j]] = 0.1f * support_tail[dim[j]] + 0.9f * vals[j];
    }
}

// ---------------------------------------------------------------------------
// K4: P = node_rep @ W1^T , Q = node_rep @ W2^T  (grid.z selects)
//     64 nodes x 96 outs. A tile stored as DUPLICATED float2 pairs so the
//     FFMA2 broadcast operand is a single LDS.64 (no pk2 MOVs).
// ---------------------------------------------------------------------------
__global__ __launch_bounds__(256) void pq_gemm(const float* __restrict__ node_rep,
                                               const float* __restrict__ W) {
    __shared__ __align__(16) float  sW[NRD][98];   // [k][o], 8B-aligned pairs
    __shared__ __align__(16) float2 sA[34][64];    // [kk][node] duplicated
    int tid = threadIdx.x;
    int z = blockIdx.z;
    int n0 = blockIdx.x * 64;
    const float* Wz = W + z * NRD;

    for (int i = tid; i < NRD * 96; i += 256) {
        int k = i % NRD, o = i / NRD;
        sW[k][o] = Wz[o * 300 + k];
    }

    u64 acc[4][3] = {};
    int ty = tid >> 4;                        // 16 groups of 4 nodes
    int tx = tid & 15;                        // 16 groups of 6 outs

    for (int k0 = 0; k0 < NRD; k0 += 34) {
        __syncthreads();
        #pragma unroll
        for (int v = 0; v < 5; v++) {
            int f = tid + v * 256;
            if (f < 64 * 17) {
                int e = f / 17;
                int kk2 = (f - e * 17) * 2;
                int n = n0 + e;
                float2 val = (n < NN)
                    ? *(const float2*)(node_rep + (size_t)n * NRD + k0 + kk2)
                    : make_float2(0.f, 0.f);
                sA[kk2][e]     = make_float2(val.x, val.x);
                sA[kk2 + 1][e] = make_float2(val.y, val.y);
            }
        }
        __syncthreads();
        #pragma unroll
        for (int kk = 0; kk < 34; kk++) {
            const u64* wp = (const u64*)&sW[k0 + kk][tx * 6];
            u64 w0 = wp[0], w1 = wp[1], w2 = wp[2];
            #pragma unroll
            for (int i2 = 0; i2 < 4; i2++) {
                u64 ap = *(const u64*)&sA[kk][ty * 4 + i2];
                acc[i2][0] = ffma2(ap, w0, acc[i2][0]);
                acc[i2][1] = ffma2(ap, w1, acc[i2][1]);
                acc[i2][2] = ffma2(ap, w2, acc[i2][2]);
            }
        }
    }

    float* out = z ? g_Q : g_P;
    #pragma unroll
    for (int i2 = 0; i2 < 4; i2++) {
        int n = n0 + ty * 4 + i2;
        if (n < NN) {
            float2* dst = (float2*)(out + (size_t)n * 96 + tx * 6);
            #pragma unroll
            for (int j2 = 0; j2 < 3; j2++) dst[j2] = up2(acc[i2][j2]);
        }
    }
}

// ---------------------------------------------------------------------------
// K5: edge_rep = attr @ W3^T + P[row] + Q[col] + b
//     128 edges x 96 outs, duplicated-pair A tile, full W3 in smem.
//     Inner loop: 8 LDS.64(a) + 3 LDS.64(w) + 24 FFMA2 per kk — no MOVs.
// ---------------------------------------------------------------------------
__global__ __launch_bounds__(256) void edge_gemm(const float* __restrict__ attr,
                                                 const float* __restrict__ W,
                                                 const float* __restrict__ b,
                                                 const int* __restrict__ ei,
                                                 float* __restrict__ out) {
    __shared__ __align__(16) float  sW[96][98];
    __shared__ __align__(16) float2 sA[16][128];   // [kk][edge] duplicated
    int tid = threadIdx.x;
    int e0 = blockIdx.x * 128;

    for (int i = tid; i < 96 * 96; i += 256) {
        int k = i % 96, o = i / 96;
        sW[k][o] = W[o * 300 + 204 + k];           // W3 slice
    }

    u64 acc[8][3] = {};
    int ty = tid >> 4;                             // 16 groups of 8 edges
    int tx = tid & 15;                             // 16 groups of 6 outs

    for (int k0 = 0; k0 < 96; k0 += 16) {
        __syncthreads();
        {
            // 256 threads cover 128 edges x 2 halves of the 16-k chunk
            int e = tid >> 1, half = tid & 1;
            const float4* src =
                (const float4*)(attr + (size_t)(e0 + e) * 96 + k0 + half * 8);
            float4 v0 = src[0], v1 = src[1];
            int kb = half * 8;
            sA[kb + 0][e] = make_float2(v0.x, v0.x);
            sA[kb + 1][e] = make_float2(v0.y, v0.y);
            sA[kb + 2][e] = make_float2(v0.z, v0.z);
            sA[kb + 3][e] = make_float2(v0.w, v0.w);
            sA[kb + 4][e] = make_float2(v1.x, v1.x);
            sA[kb + 5][e] = make_float2(v1.y, v1.y);
            sA[kb + 6][e] = make_float2(v1.z, v1.z);
            sA[kb + 7][e] = make_float2(v1.w, v1.w);
        }
        __syncthreads();
        #pragma unroll
        for (int kk = 0; kk < 16; kk++) {
            const u64* wp = (const u64*)&sW[k0 + kk][tx * 6];
            u64 w0 = wp[0], w1 = wp[1], w2 = wp[2];
            #pragma unroll
            for (int i2 = 0; i2 < 8; i2++) {
                u64 ap = *(const u64*)&sA[kk][ty * 8 + i2];
                acc[i2][0] = ffma2(ap, w0, acc[i2][0]);
                acc[i2][1] = ffma2(ap, w1, acc[i2][1]);
                acc[i2][2] = ffma2(ap, w2, acc[i2][2]);
            }
        }
    }

    float2 bv[3];
    {
        const float2* bp = (const float2*)(b + tx * 6);
        bv[0] = bp[0]; bv[1] = bp[1]; bv[2] = bp[2];
    }

    #pragma unroll
    for (int i2 = 0; i2 < 8; i2++) {
        int e = e0 + ty * 8 + i2;
        int r = ei[e];
        int c = ei[EE + e];
        const float2* Pr = (const float2*)(g_P + (size_t)r * 96 + tx * 6);
        const float2* Qc = (const float2*)(g_Q + (size_t)c * 96 + tx * 6);
        float2* dst = (float2*)(out + (size_t)e * 96 + tx * 6);
        #pragma unroll
        for (int j2 = 0; j2 < 3; j2++) {
            float2 a = up2(acc[i2][j2]);
            float2 p = Pr[j2], q = Qc[j2];
            dst[j2] = make_float2(a.x + p.x + q.x + bv[j2].x,
                                  a.y + p.y + q.y + bv[j2].y);
        }
    }
}

// ---------------------------------------------------------------------------
extern "C" void kernel_launch(void* const* d_in, const int* in_sizes, int n_in,
                              void* d_out, int out_size) {
    const int*   change = (const int*)d_in[0];
    const int*   is_sup = (const int*)d_in[1];
    const int*   tails  = (const int*)d_in[3];
    const float* x      = (const float*)d_in[4];
    const int*   ei     = (const int*)d_in[5];
    const float* attr   = (const float*)d_in[6];
    const float* mask   = (const float*)d_in[7];
    const float* stail  = (const float*)d_in[9];
    const float* W      = (const float*)d_in[10];
    const float* b      = (const float*)d_in[11];

    float* node_out = (float*)d_out;
    float* edge_out = node_out + (size_t)NN * NRD;

    init_k    <<<(NN * 24 + 255) / 256, 256>>>(x, node_out);
    scatter_k <<<(EE * 24 + 255) / 256, 256>>>(ei, attr, mask);
    finalize_k<<<(NN * 24 + 255) / 256, 256>>>(node_out);
    blend_k   <<<1, 1024>>>(change, is_sup, tails, stail, node_out);
    pq_gemm   <<<dim3((NN + 63) / 64, 1, 2), 256>>>(node_out, W);
    edge_gemm <<<EE / 128, 256>>>(attr, W, b, ei, edge_out);
}

// round 5
// speedup vs baseline: 1.2590x; 1.2590x over previous
#include <cuda_runtime.h>
#include <cuda_bf16.h>
#include <cstdint>

#define NN  100000
#define EE  800000
#define DD  96
#define NRD 102   // D + XD

typedef unsigned long long u64;

__device__ __forceinline__ u64 pk2(float lo, float hi) {
    u64 r; asm("mov.b64 %0,{%1,%2};" : "=l"(r) : "f"(lo), "f"(hi)); return r;
}
__device__ __forceinline__ u64 ffma2(u64 a, u64 b, u64 c) {
    u64 d; asm("fma.rn.f32x2 %0,%1,%2,%3;" : "=l"(d) : "l"(a), "l"(b), "l"(c)); return d;
}
__device__ __forceinline__ float2 up2(u64 v) {
    float2 f; asm("mov.b64 {%0,%1},%2;" : "=f"(f.x), "=f"(f.y) : "l"(v)); return f;
}

// ---- scratch (device globals; no allocation allowed) ----
__device__ __align__(16) float4 g_num4[NN * 24];   // [N,96] accumulator
__device__ float  g_den[NN];
__device__ __align__(16) float g_P[NN * DD];       // node_rep @ W1^T
__device__ __align__(16) float g_Q[NN * DD];       // node_rep @ W2^T

// ---------------------------------------------------------------------------
// K0: zero accumulators, write x into node_rep columns 96..101
// ---------------------------------------------------------------------------
__global__ void init_k(const float* __restrict__ x, float* __restrict__ node_out) {
    int i = blockIdx.x * 256 + threadIdx.x;
    if (i < NN * 24) g_num4[i] = make_float4(0.f, 0.f, 0.f, 0.f);
    if (i < NN)      g_den[i] = 0.f;
    if (i < NN * 6)  node_out[(i / 6) * NRD + 96 + (i % 6)] = x[i];
}

// ---------------------------------------------------------------------------
// K1: masked scatter-sum via vector reduction atomics (one thread per quad)
// ---------------------------------------------------------------------------
__global__ void scatter_k(const int* __restrict__ ei,
                          const float* __restrict__ attr,
                          const float* __restrict__ mask) {
    int i = blockIdx.x * 256 + threadIdx.x;
    if (i >= EE * 24) return;
    int e = i / 24;
    int q = i - e * 24;
    int c = ei[EE + e];
    float m = mask[e];
    float4 v = *(const float4*)(attr + (size_t)e * 96 + q * 4);
    float* dst = ((float*)g_num4) + (size_t)c * 96 + q * 4;
    asm volatile("red.global.add.v4.f32 [%0], {%1,%2,%3,%4};"
                 :: "l"(dst), "f"(v.x * m), "f"(v.y * m), "f"(v.z * m), "f"(v.w * m)
                 : "memory");
    if (q == 0) atomicAdd(&g_den[c], m);
}

// ---------------------------------------------------------------------------
// K2: node_rep[:, :96] = num / (den + 1)
// ---------------------------------------------------------------------------
__global__ void finalize_k(float* __restrict__ node_out) {
    int i = blockIdx.x * 256 + threadIdx.x;
    if (i >= NN * 24) return;
    int n = i / 24;
    int q = i - n * 24;
    float inv = 1.f / (g_den[n] + 1.f);
    float4 v = g_num4[i];
    float* dst = node_out + (size_t)n * NRD + q * 4;
    dst[0] = v.x * inv; dst[1] = v.y * inv; dst[2] = v.z * inv; dst[3] = v.w * inv;
}

// ---------------------------------------------------------------------------
// K3: tail-row blend, parallel: gather-all -> sync -> write-all (one block)
// ---------------------------------------------------------------------------
__global__ void blend_k(const int* __restrict__ change,
                        const int* __restrict__ is_support,
                        const int* __restrict__ tails,
                        const float* __restrict__ support_tail,
                        float* __restrict__ node_out) {
    if (change[0] == 0) return;
    const int TOT = 128 * NRD;
    int tid = threadIdx.x;
    float vals[13];
    int   addr[13];
    short dim[13];
    int cnt = 0;
    for (int i = tid; i < TOT; i += 1024) {
        int t = i / NRD, d = i - t * NRD;
        int node = tails[t];
        addr[cnt] = node * NRD + d;
        dim[cnt]  = (short)d;
        vals[cnt] = node_out[addr[cnt]];
        cnt++;
    }
    if (is_support[0]) {
        __shared__ float ssum[NRD];
        for (int d = tid; d < NRD; d += 1024) ssum[d] = 0.f;
        __syncthreads();
        for (int j = 0; j < cnt; j++) atomicAdd(&ssum[dim[j]], vals[j]);
        __syncthreads();
        for (int j = 0; j < cnt; j++)
            node_out[addr[j]] = ssum[dim[j]] * (1.f / 128.f);
    } else {
        __syncthreads();
        for (int j = 0; j < cnt; j++)
            node_out[addr[j]] = 0.1f * support_tail[dim[j]] + 0.9f * vals[j];
    }
}

// ---------------------------------------------------------------------------
// K4: P/Q GEMM — R2 version (proven 704us build)
// ---------------------------------------------------------------------------
__global__ __launch_bounds__(256) void pq_gemm(const float* __restrict__ node_rep,
                                               const float* __restrict__ W) {
    __shared__ __align__(16) float sW[NRD][98];
    __shared__ __align__(16) float sA[64][35];
    int tid = threadIdx.x;
    int z = blockIdx.z;
    int n0 = blockIdx.x * 64;
    const float* Wz = W + z * NRD;

    for (int i = tid; i < NRD * 96; i += 256) {
        int k = i % NRD, o = i / NRD;
        sW[k][o] = Wz[o * 300 + k];
    }

    u64 acc[4][3] = {};
    int ty = tid >> 4;
    int tx = tid & 15;

    for (int k0 = 0; k0 < NRD; k0 += 34) {
        __syncthreads();
        #pragma unroll
        for (int v = 0; v < 5; v++) {
            int f = tid + v * 256;
            if (f < 64 * 17) {
                int e = f / 17;
                int kk2 = (f - e * 17) * 2;
                int n = n0 + e;
                float2 val = (n < NN)
                    ? *(const float2*)(node_rep + (size_t)n * NRD + k0 + kk2)
                    : make_float2(0.f, 0.f);
                sA[e][kk2] = val.x; sA[e][kk2 + 1] = val.y;
            }
        }
        __syncthreads();
        #pragma unroll
        for (int kk = 0; kk < 34; kk++) {
            const u64* wp = (const u64*)&sW[k0 + kk][tx * 6];
            u64 w0 = wp[0], w1 = wp[1], w2 = wp[2];
            #pragma unroll
            for (int i2 = 0; i2 < 4; i2++) {
                float a = sA[ty * 4 + i2][kk];
                u64 ap = pk2(a, a);
                acc[i2][0] = ffma2(ap, w0, acc[i2][0]);
                acc[i2][1] = ffma2(ap, w1, acc[i2][1]);
                acc[i2][2] = ffma2(ap, w2, acc[i2][2]);
            }
        }
    }

    float* out = z ? g_Q : g_P;
    #pragma unroll
    for (int i2 = 0; i2 < 4; i2++) {
        int n = n0 + ty * 4 + i2;
        if (n < NN) {
            float2* dst = (float2*)(out + (size_t)n * 96 + tx * 6);
            #pragma unroll
            for (int j2 = 0; j2 < 3; j2++) dst[j2] = up2(acc[i2][j2]);
        }
    }
}

// ---------------------------------------------------------------------------
// K5: edge_rep via mma.sync bf16 3-term split (base-target HMMA, no tcgen05).
//   Tile: 128 edges x 96 outs. D = Ah*Bh + Ah*Bl + Al*Bh, fp32 accumulate.
//   K chunked 3x32; smem 32KB; fragments via direct conflict-free LDS.32.
// ---------------------------------------------------------------------------
#define KC      32
#define RSTRIDE 72          // (KC+4) bf16 * 2B: 18 words -> conflict-free

__device__ __forceinline__ void split2(float f0, float f1, uint32_t& hi, uint32_t& lo) {
    __nv_bfloat16 h0 = __float2bfloat16(f0), h1 = __float2bfloat16(f1);
    float l0 = f0 - __bfloat162float(h0);
    float l1 = f1 - __bfloat162float(h1);
    __nv_bfloat16 g0 = __float2bfloat16(l0), g1 = __float2bfloat16(l1);
    hi = ((uint32_t)__bfloat16_as_ushort(h1) << 16) | __bfloat16_as_ushort(h0);
    lo = ((uint32_t)__bfloat16_as_ushort(g1) << 16) | __bfloat16_as_ushort(g0);
}

__device__ __forceinline__ void mma_bf16(float4& c,
                                         uint32_t a0, uint32_t a1, uint32_t a2, uint32_t a3,
                                         uint32_t b0, uint32_t b1) {
    asm volatile(
        "mma.sync.aligned.m16n8k16.row.col.f32.bf16.bf16.f32 "
        "{%0,%1,%2,%3}, {%4,%5,%6,%7}, {%8,%9}, {%0,%1,%2,%3};"
        : "+f"(c.x), "+f"(c.y), "+f"(c.z), "+f"(c.w)
        : "r"(a0), "r"(a1), "r"(a2), "r"(a3), "r"(b0), "r"(b1));
}

__global__ __launch_bounds__(256) void edge_mma(const float* __restrict__ attr,
                                                const float* __restrict__ W,
                                                const float* __restrict__ b,
                                                const int* __restrict__ ei,
                                                float* __restrict__ out) {
    __shared__ __align__(16) char sAhi[128 * RSTRIDE];   //  9216 B
    __shared__ __align__(16) char sAlo[128 * RSTRIDE];
    __shared__ __align__(16) char sBhi[96 * RSTRIDE];    //  6912 B
    __shared__ __align__(16) char sBlo[96 * RSTRIDE];

    int tid = threadIdx.x, lane = tid & 31, w = tid >> 5;
    size_t e0 = (size_t)blockIdx.x * 128;

    int mrow = w * 16 + (lane >> 2);       // a-frag row (and +8)
    int kq   = lane & 3;                   // k-pair index within k16
    int ncol = lane >> 2;                  // b-frag n within tile

    float4 acc[12];
    #pragma unroll
    for (int t = 0; t < 12; t++) acc[t] = make_float4(0.f, 0.f, 0.f, 0.f);

    for (int kc0 = 0; kc0 < 96; kc0 += KC) {
        __syncthreads();
        // convert A chunk: 128 rows x 32 k  (8 float4 per row)
        #pragma unroll
        for (int v = 0; v < 4; v++) {
            int f = tid + v * 256;          // 1024 = 128 x 8
            int r = f >> 3, q4 = f & 7;
            float4 val = *(const float4*)(attr + (e0 + r) * 96 + kc0 + q4 * 4);
            uint32_t h01, l01, h23, l23;
            split2(val.x, val.y, h01, l01);
            split2(val.z, val.w, h23, l23);
            int off = r * RSTRIDE + q4 * 8;
            *(uint2*)(sAhi + off) = make_uint2(h01, h23);
            *(uint2*)(sAlo + off) = make_uint2(l01, l23);
        }
        // convert B chunk: 96 outs x 32 k
        #pragma unroll
        for (int v = 0; v < 3; v++) {
            int f = tid + v * 256;          // 768 = 96 x 8
            int o = f >> 3, q4 = f & 7;
            float4 val = *(const float4*)(W + o * 300 + 204 + kc0 + q4 * 4);
            uint32_t h01, l01, h23, l23;
            split2(val.x, val.y, h01, l01);
            split2(val.z, val.w, h23, l23);
            int off = o * RSTRIDE + q4 * 8;
            *(uint2*)(sBhi + off) = make_uint2(h01, h23);
            *(uint2*)(sBlo + off) = make_uint2(l01, l23);
        }
        __syncthreads();

        #pragma unroll
        for (int kc16 = 0; kc16 < 2; kc16++) {
            int kb = kc16 * 32 + kq * 4;   // byte offset within row
            const char* pa = sAhi + mrow * RSTRIDE + kb;
            uint32_t ah0 = *(const uint32_t*)(pa);
            uint32_t ah1 = *(const uint32_t*)(pa + 8 * RSTRIDE);
            uint32_t ah2 = *(const uint32_t*)(pa + 16);
            uint32_t ah3 = *(const uint32_t*)(pa + 8 * RSTRIDE + 16);
            const char* pl = sAlo + mrow * RSTRIDE + kb;
            uint32_t al0 = *(const uint32_t*)(pl);
            uint32_t al1 = *(const uint32_t*)(pl + 8 * RSTRIDE);
            uint32_t al2 = *(const uint32_t*)(pl + 16);
            uint32_t al3 = *(const uint32_t*)(pl + 8 * RSTRIDE + 16);
            #pragma unroll
            for (int t = 0; t < 12; t++) {
                int n = t * 8 + ncol;
                const char* pbh = sBhi + n * RSTRIDE + kb;
                const char* pbl = sBlo + n * RSTRIDE + kb;
                uint32_t bh0 = *(const uint32_t*)(pbh);
                uint32_t bh1 = *(const uint32_t*)(pbh + 16);
                uint32_t bl0 = *(const uint32_t*)(pbl);
                uint32_t bl1 = *(const uint32_t*)(pbl + 16);
                mma_bf16(acc[t], ah0, ah1, ah2, ah3, bh0, bh1);
                mma_bf16(acc[t], ah0, ah1, ah2, ah3, bl0, bl1);
                mma_bf16(acc[t], al0, al1, al2, al3, bh0, bh1);
            }
        }
    }

    // epilogue: thread owns rows mrow, mrow+8; cols t*8 + kq*2 (+1)
    int er0 = (int)e0 + mrow;
    int er1 = er0 + 8;
    int r0i = ei[er0], c0i = ei[EE + er0];
    int r1i = ei[er1], c1i = ei[EE + er1];
    const float* P0 = g_P + (size_t)r0i * 96;
    const float* Q0 = g_Q + (size_t)c0i * 96;
    const float* P1 = g_P + (size_t)r1i * 96;
    const float* Q1 = g_Q + (size_t)c1i * 96;
    float* o0 = out + (size_t)er0 * 96;
    float* o1 = out + (size_t)er1 * 96;
    #pragma unroll
    for (int t = 0; t < 12; t++) {
        int col = t * 8 + kq * 2;
        float2 bv = *(const float2*)(b + col);
        float2 p0 = *(const float2*)(P0 + col), q0 = *(const float2*)(Q0 + col);
        *(float2*)(o0 + col) = make_float2(acc[t].x + p0.x + q0.x + bv.x,
                                           acc[t].y + p0.y + q0.y + bv.y);
        float2 p1 = *(const float2*)(P1 + col), q1 = *(const float2*)(Q1 + col);
        *(float2*)(o1 + col) = make_float2(acc[t].z + p1.x + q1.x + bv.x,
                                           acc[t].w + p1.y + q1.y + bv.y);
    }
}

// ---------------------------------------------------------------------------
extern "C" void kernel_launch(void* const* d_in, const int* in_sizes, int n_in,
                              void* d_out, int out_size) {
    const int*   change = (const int*)d_in[0];
    const int*   is_sup = (const int*)d_in[1];
    const int*   tails  = (const int*)d_in[3];
    const float* x      = (const float*)d_in[4];
    const int*   ei     = (const int*)d_in[5];
    const float* attr   = (const float*)d_in[6];
    const float* mask   = (const float*)d_in[7];
    const float* stail  = (const float*)d_in[9];
    const float* W      = (const float*)d_in[10];
    const float* b      = (const float*)d_in[11];

    float* node_out = (float*)d_out;
    float* edge_out = node_out + (size_t)NN * NRD;

    init_k    <<<(NN * 24 + 255) / 256, 256>>>(x, node_out);
    scatter_k <<<(EE * 24 + 255) / 256, 256>>>(ei, attr, mask);
    finalize_k<<<(NN * 24 + 255) / 256, 256>>>(node_out);
    blend_k   <<<1, 1024>>>(change, is_sup, tails, stail, node_out);
    pq_gemm   <<<dim3((NN + 63) / 64, 1, 2), 256>>>(node_out, W);
    edge_mma  <<<EE / 128, 256>>>(attr, W, b, ei, edge_out);
}

// round 6
// speedup vs baseline: 1.3230x; 1.0508x over previous
#include <cuda_runtime.h>
#include <cuda_bf16.h>
#include <cstdint>

#define NN  100000
#define EE  800000
#define DD  96
#define NRD 102   // D + XD

typedef unsigned long long u64;

__device__ __forceinline__ u64 pk2(float lo, float hi) {
    u64 r; asm("mov.b64 %0,{%1,%2};" : "=l"(r) : "f"(lo), "f"(hi)); return r;
}
__device__ __forceinline__ u64 ffma2(u64 a, u64 b, u64 c) {
    u64 d; asm("fma.rn.f32x2 %0,%1,%2,%3;" : "=l"(d) : "l"(a), "l"(b), "l"(c)); return d;
}
__device__ __forceinline__ float2 up2(u64 v) {
    float2 f; asm("mov.b64 {%0,%1},%2;" : "=f"(f.x), "=f"(f.y) : "l"(v)); return f;
}
__device__ __forceinline__ uint32_t smem_u32(const void* p) {
    uint32_t a;
    asm("{ .reg .u64 t; cvta.to.shared.u64 t, %1; cvt.u32.u64 %0, t; }" : "=r"(a) : "l"(p));
    return a;
}

// ---- scratch (device globals; no allocation allowed) ----
__device__ __align__(16) float4 g_num4[NN * 24];
__device__ float  g_den[NN];
__device__ __align__(16) float g_P[NN * DD];
__device__ __align__(16) float g_Q[NN * DD];
__device__ __align__(16) uint4 g_W3hi[96 * 192 / 16];   // bf16 [96 o][96 k]
__device__ __align__(16) uint4 g_W3lo[96 * 192 / 16];

// ---------------------------------------------------------------------------
__global__ void init_k(const float* __restrict__ x, float* __restrict__ node_out) {
    int i = blockIdx.x * 256 + threadIdx.x;
    if (i < NN * 24) g_num4[i] = make_float4(0.f, 0.f, 0.f, 0.f);
    if (i < NN)      g_den[i] = 0.f;
    if (i < NN * 6)  node_out[(i / 6) * NRD + 96 + (i % 6)] = x[i];
}

// ---------------------------------------------------------------------------
__global__ void scatter_k(const int* __restrict__ ei,
                          const float* __restrict__ attr,
                          const float* __restrict__ mask) {
    int i = blockIdx.x * 256 + threadIdx.x;
    if (i >= EE * 24) return;
    int e = i / 24;
    int q = i - e * 24;
    int c = ei[EE + e];
    float m = mask[e];
    float4 v = *(const float4*)(attr + (size_t)e * 96 + q * 4);
    float* dst = ((float*)g_num4) + (size_t)c * 96 + q * 4;
    asm volatile("red.global.add.v4.f32 [%0], {%1,%2,%3,%4};"
                 :: "l"(dst), "f"(v.x * m), "f"(v.y * m), "f"(v.z * m), "f"(v.w * m)
                 : "memory");
    if (q == 0) atomicAdd(&g_den[c], m);
}

// ---------------------------------------------------------------------------
__global__ void finalize_k(float* __restrict__ node_out) {
    int i = blockIdx.x * 256 + threadIdx.x;
    if (i >= NN * 24) return;
    int n = i / 24;
    int q = i - n * 24;
    float inv = 1.f / (g_den[n] + 1.f);
    float4 v = g_num4[i];
    float* dst = node_out + (size_t)n * NRD + q * 4;
    dst[0] = v.x * inv; dst[1] = v.y * inv; dst[2] = v.z * inv; dst[3] = v.w * inv;
}

// ---------------------------------------------------------------------------
__global__ void blend_k(const int* __restrict__ change,
                        const int* __restrict__ is_support,
                        const int* __restrict__ tails,
                        const float* __restrict__ support_tail,
                        float* __restrict__ node_out) {
    if (change[0] == 0) return;
    const int TOT = 128 * NRD;
    int tid = threadIdx.x;
    float vals[13];
    int   addr[13];
    short dim[13];
    int cnt = 0;
    for (int i = tid; i < TOT; i += 1024) {
        int t = i / NRD, d = i - t * NRD;
        int node = tails[t];
        addr[cnt] = node * NRD + d;
        dim[cnt]  = (short)d;
        vals[cnt] = node_out[addr[cnt]];
        cnt++;
    }
    if (is_support[0]) {
        __shared__ float ssum[NRD];
        for (int d = tid; d < NRD; d += 1024) ssum[d] = 0.f;
        __syncthreads();
        for (int j = 0; j < cnt; j++) atomicAdd(&ssum[dim[j]], vals[j]);
        __syncthreads();
        for (int j = 0; j < cnt; j++)
            node_out[addr[j]] = ssum[dim[j]] * (1.f / 128.f);
    } else {
        __syncthreads();
        for (int j = 0; j < cnt; j++)
            node_out[addr[j]] = 0.1f * support_tail[dim[j]] + 0.9f * vals[j];
    }
}

// ---------------------------------------------------------------------------
// bf16 split helpers (cvt.rn.bf16x2.f32: 2 elems per instruction)
// ---------------------------------------------------------------------------
__device__ __forceinline__ void split4(float4 v, uint2& hi, uint2& lo) {
    uint32_t h01, h23, l01, l23;
    asm("cvt.rn.bf16x2.f32 %0, %1, %2;" : "=r"(h01) : "f"(v.y), "f"(v.x));
    asm("cvt.rn.bf16x2.f32 %0, %1, %2;" : "=r"(h23) : "f"(v.w), "f"(v.z));
    float r0 = v.x - __uint_as_float(h01 << 16);
    float r1 = v.y - __uint_as_float(h01 & 0xFFFF0000u);
    float r2 = v.z - __uint_as_float(h23 << 16);
    float r3 = v.w - __uint_as_float(h23 & 0xFFFF0000u);
    asm("cvt.rn.bf16x2.f32 %0, %1, %2;" : "=r"(l01) : "f"(r1), "f"(r0));
    asm("cvt.rn.bf16x2.f32 %0, %1, %2;" : "=r"(l23) : "f"(r3), "f"(r2));
    hi = make_uint2(h01, h23); lo = make_uint2(l01, l23);
}

// one-time W3 split: [96 o][96 k] fp32 -> bf16 hi/lo
__global__ void w_prep(const float* __restrict__ W) {
    int tid = threadIdx.x;
    for (int i = tid; i < 96 * 24; i += 256) {
        int o = i / 24, q = i % 24;
        float4 v = *(const float4*)(W + o * 300 + 204 + q * 4);
        uint2 hi, lo;
        split4(v, hi, lo);
        *((uint2*)g_W3hi + o * 24 + q) = hi;
        *((uint2*)g_W3lo + o * 24 + q) = lo;
    }
}

// ---------------------------------------------------------------------------
// K4: P/Q GEMM — proven R2 version
// ---------------------------------------------------------------------------
__global__ __launch_bounds__(256) void pq_gemm(const float* __restrict__ node_rep,
                                               const float* __restrict__ W) {
    __shared__ __align__(16) float sW[NRD][98];
    __shared__ __align__(16) float sA[64][35];
    int tid = threadIdx.x;
    int z = blockIdx.z;
    int n0 = blockIdx.x * 64;
    const float* Wz = W + z * NRD;

    for (int i = tid; i < NRD * 96; i += 256) {
        int k = i % NRD, o = i / NRD;
        sW[k][o] = Wz[o * 300 + k];
    }

    u64 acc[4][3] = {};
    int ty = tid >> 4;
    int tx = tid & 15;

    for (int k0 = 0; k0 < NRD; k0 += 34) {
        __syncthreads();
        #pragma unroll
        for (int v = 0; v < 5; v++) {
            int f = tid + v * 256;
            if (f < 64 * 17) {
                int e = f / 17;
                int kk2 = (f - e * 17) * 2;
                int n = n0 + e;
                float2 val = (n < NN)
                    ? *(const float2*)(node_rep + (size_t)n * NRD + k0 + kk2)
                    : make_float2(0.f, 0.f);
                sA[e][kk2] = val.x; sA[e][kk2 + 1] = val.y;
            }
        }
        __syncthreads();
        #pragma unroll
        for (int kk = 0; kk < 34; kk++) {
            const u64* wp = (const u64*)&sW[k0 + kk][tx * 6];
            u64 w0 = wp[0], w1 = wp[1], w2 = wp[2];
            #pragma unroll
            for (int i2 = 0; i2 < 4; i2++) {
                float a = sA[ty * 4 + i2][kk];
                u64 ap = pk2(a, a);
                acc[i2][0] = ffma2(ap, w0, acc[i2][0]);
                acc[i2][1] = ffma2(ap, w1, acc[i2][1]);
                acc[i2][2] = ffma2(ap, w2, acc[i2][2]);
            }
        }
    }

    float* out = z ? g_Q : g_P;
    #pragma unroll
    for (int i2 = 0; i2 < 4; i2++) {
        int n = n0 + ty * 4 + i2;
        if (n < NN) {
            float2* dst = (float2*)(out + (size_t)n * 96 + tx * 6);
            #pragma unroll
            for (int j2 = 0; j2 < 3; j2++) dst[j2] = up2(acc[i2][j2]);
        }
    }
}

// ---------------------------------------------------------------------------
// K5: edge_rep via mma.sync bf16 3-term split, ldmatrix fragment loads.
// ---------------------------------------------------------------------------
#define RS 80           // row stride bytes (64B data + 16B pad, conflict-free)

__device__ __forceinline__ void ldsm4(uint32_t addr, uint32_t* r) {
    asm volatile("ldmatrix.sync.aligned.m8n8.x4.shared.b16 {%0,%1,%2,%3}, [%4];"
                 : "=r"(r[0]), "=r"(r[1]), "=r"(r[2]), "=r"(r[3]) : "r"(addr));
}
__device__ __forceinline__ void mma_bf16(float4& c, const uint32_t* a,
                                         uint32_t b0, uint32_t b1) {
    asm volatile(
        "mma.sync.aligned.m16n8k16.row.col.f32.bf16.bf16.f32 "
        "{%0,%1,%2,%3}, {%4,%5,%6,%7}, {%8,%9}, {%0,%1,%2,%3};"
        : "+f"(c.x), "+f"(c.y), "+f"(c.z), "+f"(c.w)
        : "r"(a[0]), "r"(a[1]), "r"(a[2]), "r"(a[3]), "r"(b0), "r"(b1));
}

__global__ __launch_bounds__(256) void edge_mma(const float* __restrict__ attr,
                                                const float* __restrict__ b,
                                                const int* __restrict__ ei,
                                                float* __restrict__ out) {
    __shared__ __align__(16) char sAhi[128 * RS];   // 10240 B
    __shared__ __align__(16) char sAlo[128 * RS];
    __shared__ __align__(16) char sBhi[96 * RS];    //  7680 B
    __shared__ __align__(16) char sBlo[96 * RS];

    int tid = threadIdx.x, lane = tid & 31, w = tid >> 5;
    size_t e0 = (size_t)blockIdx.x * 128;

    uint32_t aHi = smem_u32(sAhi), aLo = smem_u32(sAlo);
    uint32_t bHi = smem_u32(sBhi), bLo = smem_u32(sBlo);

    // ldmatrix lane addressing
    uint32_t aoff = (uint32_t)(w * 16 + (lane & 15)) * RS + ((lane >> 4) & 1) * 16;
    uint32_t brow = (uint32_t)(lane & 7) * RS + ((lane >> 3) & 1) * 16; // + tilepair base
    uint32_t btp  = ((lane >> 4) & 1) * 8 * RS;

    float4 acc[12];
    #pragma unroll
    for (int t = 0; t < 12; t++) acc[t] = make_float4(0.f, 0.f, 0.f, 0.f);

    for (int kc0 = 0; kc0 < 96; kc0 += 32) {
        __syncthreads();
        // A chunk: 128 rows x 32 k -> split to bf16 hi/lo
        #pragma unroll
        for (int v = 0; v < 4; v++) {
            int f = tid + v * 256;               // 1024 = 128 rows x 8 quads
            int r = f >> 3, q4 = f & 7;
            float4 val = *(const float4*)(attr + (e0 + r) * 96 + kc0 + q4 * 4);
            uint2 hi, lo;
            split4(val, hi, lo);
            int off = r * RS + q4 * 8;
            *(uint2*)(sAhi + off) = hi;
            *(uint2*)(sAlo + off) = lo;
        }
        // B chunk: copy precomputed bf16 W3 rows (64B per row per chunk)
        {
            int kq = kc0 >> 3;                   // uint4 offset within row (192B = 12)
            #pragma unroll
            for (int v = 0; v < 3; v++) {
                int f = tid + v * 256;           // 768 = 2 arrays x 96 rows x 4 uint4
                int sel = f >= 384;
                int g = sel ? f - 384 : f;
                int o = g >> 2, q = g & 3;
                uint4 val = (sel ? g_W3lo : g_W3hi)[o * 12 + kq + q];
                *(uint4*)((sel ? sBlo : sBhi) + o * RS + q * 16) = val;
            }
        }
        __syncthreads();

        #pragma unroll
        for (int kc16 = 0; kc16 < 2; kc16++) {
            uint32_t ah[4], al[4];
            ldsm4(aHi + aoff + kc16 * 32, ah);
            ldsm4(aLo + aoff + kc16 * 32, al);
            #pragma unroll
            for (int tp = 0; tp < 6; tp++) {
                uint32_t bh[4], bl[4];
                uint32_t bo = (uint32_t)(tp * 16) * RS + btp + brow + kc16 * 32;
                ldsm4(bHi + bo, bh);
                ldsm4(bLo + bo, bl);
                mma_bf16(acc[tp * 2],     ah, bh[0], bh[1]);
                mma_bf16(acc[tp * 2],     ah, bl[0], bl[1]);
                mma_bf16(acc[tp * 2],     al, bh[0], bh[1]);
                mma_bf16(acc[tp * 2 + 1], ah, bh[2], bh[3]);
                mma_bf16(acc[tp * 2 + 1], ah, bl[2], bl[3]);
                mma_bf16(acc[tp * 2 + 1], al, bh[2], bh[3]);
            }
        }
    }

    // epilogue: thread owns rows mrow, mrow+8; cols t*8 + kq*2
    int mrow = w * 16 + (lane >> 2);
    int kq = lane & 3;
    int er0 = (int)e0 + mrow;
    int er1 = er0 + 8;
    int r0i = ei[er0], c0i = ei[EE + er0];
    int r1i = ei[er1], c1i = ei[EE + er1];
    const float* P0 = g_P + (size_t)r0i * 96;
    const float* Q0 = g_Q + (size_t)c0i * 96;
    const float* P1 = g_P + (size_t)r1i * 96;
    const float* Q1 = g_Q + (size_t)c1i * 96;
    float* o0 = out + (size_t)er0 * 96;
    float* o1 = out + (size_t)er1 * 96;
    #pragma unroll
    for (int t = 0; t < 12; t++) {
        int col = t * 8 + kq * 2;
        float2 bv = *(const float2*)(b + col);
        float2 p0 = *(const float2*)(P0 + col), q0 = *(const float2*)(Q0 + col);
        *(float2*)(o0 + col) = make_float2(acc[t].x + p0.x + q0.x + bv.x,
                                           acc[t].y + p0.y + q0.y + bv.y);
        float2 p1 = *(const float2*)(P1 + col), q1 = *(const float2*)(Q1 + col);
        *(float2*)(o1 + col) = make_float2(acc[t].z + p1.x + q1.x + bv.x,
                                           acc[t].w + p1.y + q1.y + bv.y);
    }
}

// ---------------------------------------------------------------------------
extern "C" void kernel_launch(void* const* d_in, const int* in_sizes, int n_in,
                              void* d_out, int out_size) {
    const int*   change = (const int*)d_in[0];
    const int*   is_sup = (const int*)d_in[1];
    const int*   tails  = (const int*)d_in[3];
    const float* x      = (const float*)d_in[4];
    const int*   ei     = (const int*)d_in[5];
    const float* attr   = (const float*)d_in[6];
    const float* mask   = (const float*)d_in[7];
    const float* stail  = (const float*)d_in[9];
    const float* W      = (const float*)d_in[10];
    const float* b      = (const float*)d_in[11];

    float* node_out = (float*)d_out;
    float* edge_out = node_out + (size_t)NN * NRD;

    init_k    <<<(NN * 24 + 255) / 256, 256>>>(x, node_out);
    w_prep    <<<1, 256>>>(W);
    scatter_k <<<(EE * 24 + 255) / 256, 256>>>(ei, attr, mask);
    finalize_k<<<(NN * 24 + 255) / 256, 256>>>(node_out);
    blend_k   <<<1, 1024>>>(change, is_sup, tails, stail, node_out);
    pq_gemm   <<<dim3((NN + 63) / 64, 1, 2), 256>>>(node_out, W);
    edge_mma  <<<EE / 128, 256>>>(attr, b, ei, edge_out);
}